// round 1
// baseline (speedup 1.0000x reference)
#include <cuda_runtime.h>
#include <cuda_bf16.h>
#include <math.h>

// Problem constants
#define L_SEQ 2048
#define E_DIM 512
#define H2    512
#define NT    12
#define START 10
#define STOP  11
#define NEGV  -10000.0f

#define NCTA_DIR 64           // CTAs per direction
#define ROWS_PER_CTA 8        // hidden units per CTA
#define GROWS (4*ROWS_PER_CTA) // gate rows per CTA = 32

// ---------------- device scratch (no cudaMalloc allowed) ----------------
__device__ float g_xs[L_SEQ * E_DIM];              // embedded sentence, 4 MB
__device__ float g_hs[2][(L_SEQ + 1) * H2];        // h history per direction (slot 0 = h0)
__device__ float g_feats[L_SEQ * NT];
__device__ float g_chunk[128][NT * NT];            // CRF chunk matrices
__device__ unsigned g_cnt[2];
__device__ unsigned g_gen[2];

// ---------------- init: embedding gather + barrier/h0 init ----------------
__global__ void init_kernel(const int* __restrict__ sentence,
                            const float* __restrict__ emb,
                            const float* __restrict__ h0)
{
    int b = blockIdx.x;
    if (b < L_SEQ) {
        int row = sentence[b];
        const float4* src = (const float4*)(emb + (size_t)row * E_DIM);
        float4* dst = (float4*)(g_xs + (size_t)b * E_DIM);
        dst[threadIdx.x] = src[threadIdx.x];   // 128 threads x float4 = 512 floats
    } else {
        if (threadIdx.x < 2) { g_cnt[threadIdx.x] = 0; g_gen[threadIdx.x] = 0; }
        // copy h0 (2 x 512) into history slot 0 of each direction
        const float4* s = (const float4*)h0;
        for (int i = threadIdx.x; i < 2 * (H2 / 4); i += 128) {
            int d = i >> 7;        // 128 float4 per direction
            int q = i & 127;
            ((float4*)(g_hs[d]))[q] = s[i];
        }
    }
}

// ---------------- persistent bidirectional LSTM scan ----------------
// 128 CTAs: dir = bid/64, sub = bid%64. Each CTA owns hidden units [sub*8, sub*8+8)
// and keeps the 32 corresponding gate rows of W_ih and W_hh in SMEM (128 KB).
__global__ void __launch_bounds__(256, 1) lstm_kernel(
    const float* __restrict__ Wihf, const float* __restrict__ Whhf, const float* __restrict__ bf,
    const float* __restrict__ Wihb, const float* __restrict__ Whhb, const float* __restrict__ bb,
    const float* __restrict__ c0)
{
    extern __shared__ float sm[];
    float* Wih_s  = sm;                       // 32*512
    float* Whh_s  = sm + GROWS * E_DIM;       // 32*512
    float* hv     = sm + 2 * GROWS * E_DIM;   // 512
    float* xv     = hv + H2;                  // 512
    float* bias_s = xv + E_DIM;               // 32
    float* gsum   = bias_s + GROWS;           // 32
    float* c_s    = gsum + GROWS;             // 8

    const int dir = blockIdx.x / NCTA_DIR;
    const int sub = blockIdx.x % NCTA_DIR;
    const int k0  = sub * ROWS_PER_CTA;
    const float* Wih = dir ? Wihb : Wihf;
    const float* Whh = dir ? Whhb : Whhf;
    const float* bv  = dir ? bb  : bf;
    const int tid = threadIdx.x;

    // load this CTA's weight slices into SMEM (one time)
    for (int i = tid; i < GROWS * (E_DIM / 4); i += 256) {
        int lr = i >> 7;          // local gate row 0..31
        int c4 = i & 127;
        int g = lr >> 3, k = lr & 7;
        size_t gr = (size_t)(g * H2 + k0 + k);
        ((float4*)Wih_s)[i] = ((const float4*)(Wih + gr * E_DIM))[c4];
        ((float4*)Whh_s)[i] = ((const float4*)(Whh + gr * H2))[c4];
    }
    if (tid < GROWS) {
        int g = tid >> 3, k = tid & 7;
        bias_s[tid] = bv[g * H2 + k0 + k];
    }
    if (tid < ROWS_PER_CTA) c_s[tid] = c0[dir * H2 + k0 + tid];
    __syncthreads();

    float* hist = g_hs[dir];
    const int w = tid >> 5, l = tid & 31;

    for (int t = 0; t < L_SEQ; ++t) {
        const int pos = dir ? (L_SEQ - 1 - t) : t;
        // stage h_{t-1} and x_t into SMEM
        if (tid < 128)       ((float4*)hv)[tid]       = ((const float4*)(hist + (size_t)t * H2))[tid];
        else                 ((float4*)xv)[tid - 128] = ((const float4*)(g_xs + (size_t)pos * E_DIM))[tid - 128];
        __syncthreads();

        // GEMV: warp w computes gate rows 4w..4w+3; lane covers float4 cols l+32j
        float4 h4[4], x4[4];
        #pragma unroll
        for (int j = 0; j < 4; ++j) {
            h4[j] = ((float4*)hv)[l + 32 * j];
            x4[j] = ((float4*)xv)[l + 32 * j];
        }
        #pragma unroll
        for (int r = 0; r < 4; ++r) {
            int lr = w * 4 + r;
            float acc = 0.f;
            #pragma unroll
            for (int j = 0; j < 4; ++j) {
                float4 wh = ((float4*)Whh_s)[lr * 128 + l + 32 * j];
                float4 wi = ((float4*)Wih_s)[lr * 128 + l + 32 * j];
                acc += wh.x * h4[j].x + wh.y * h4[j].y + wh.z * h4[j].z + wh.w * h4[j].w;
                acc += wi.x * x4[j].x + wi.y * x4[j].y + wi.z * x4[j].z + wi.w * x4[j].w;
            }
            #pragma unroll
            for (int off = 16; off; off >>= 1) acc += __shfl_xor_sync(0xffffffffu, acc, off);
            if (l == 0) gsum[lr] = acc + bias_s[lr];
        }
        __syncthreads();

        // elementwise gate update for this CTA's 8 hidden units
        if (tid < ROWS_PER_CTA) {
            float ig = 1.f / (1.f + expf(-gsum[tid]));
            float fg = 1.f / (1.f + expf(-gsum[8 + tid]));
            float gg = tanhf(gsum[16 + tid]);
            float og = 1.f / (1.f + expf(-gsum[24 + tid]));
            float c = fg * c_s[tid] + ig * gg;
            c_s[tid] = c;
            hist[(size_t)(t + 1) * H2 + k0 + tid] = og * tanhf(c);
            __threadfence();
        }
        __syncthreads();

        // per-direction grid barrier (sense = generation counter)
        if (tid == 0) {
            unsigned old = atomicAdd(&g_cnt[dir], 1u);
            if (old == NCTA_DIR - 1) {
                atomicExch(&g_cnt[dir], 0u);
                __threadfence();
                atomicExch(&g_gen[dir], (unsigned)(t + 1));
            } else {
                while (*((volatile unsigned*)&g_gen[dir]) < (unsigned)(t + 1)) { }
                __threadfence();
            }
        }
        __syncthreads();
    }
}

// ---------------- output projection: feats[t][i] ----------------
__global__ void feats_kernel(const float* __restrict__ W_out, const float* __restrict__ b_out)
{
    int t = blockIdx.x;
    int w = threadIdx.x >> 5, l = threadIdx.x & 31;  // 12 warps
    const float* hf = g_hs[0] + (size_t)(t + 1) * H2;
    const float* hb = g_hs[1] + (size_t)(L_SEQ - t) * H2;  // bwd step s=L-1-t stored at s+1
    const float* wo = W_out + (size_t)w * (2 * H2);
    float acc = 0.f;
    for (int c = l; c < H2; c += 32)
        acc += hf[c] * wo[c] + hb[c] * wo[H2 + c];
    #pragma unroll
    for (int off = 16; off; off >>= 1) acc += __shfl_xor_sync(0xffffffffu, acc, off);
    if (l == 0) g_feats[t * NT + w] = acc + b_out[w];
}

// ---------------- CRF: chunked log-semiring scan ----------------
// chunk matrices: C_b = A_{16b+15} (x) ... (x) A_{16b},  A_t[i][j] = trans[i][j] + feat_t[i]
__global__ void crf_chunk_kernel(const float* __restrict__ trans)
{
    __shared__ float tr[NT * NT], cur[NT * NT];
    int tid = threadIdx.x;           // 0..143
    int i = tid / NT, j = tid % NT;
    tr[tid] = trans[tid];
    int t0 = blockIdx.x * 16;
    cur[tid] = trans[tid] + g_feats[t0 * NT + i];
    __syncthreads();
    for (int s = 1; s < 16; ++s) {
        float ft = g_feats[(t0 + s) * NT + i];
        float v[NT];
        float m = -3.4e38f;
        #pragma unroll
        for (int k = 0; k < NT; ++k) { v[k] = tr[i * NT + k] + cur[k * NT + j]; m = fmaxf(m, v[k]); }
        float ssum = 0.f;
        #pragma unroll
        for (int k = 0; k < NT; ++k) ssum += expf(v[k] - m);
        float r = ft + m + logf(ssum);
        __syncthreads();
        cur[tid] = r;
        __syncthreads();
    }
    g_chunk[blockIdx.x][tid] = cur[tid];
}

__global__ void crf_final_kernel(const float* __restrict__ trans, float* __restrict__ out)
{
    __shared__ float fv[NT], nfv[NT];
    int tid = threadIdx.x;
    if (tid < NT) fv[tid] = (tid == START) ? 0.f : NEGV;
    __syncwarp();
    for (int b = 0; b < 128; ++b) {
        if (tid < NT) {
            float m = -3.4e38f, v[NT];
            #pragma unroll
            for (int k = 0; k < NT; ++k) { v[k] = g_chunk[b][tid * NT + k] + fv[k]; m = fmaxf(m, v[k]); }
            float s = 0.f;
            #pragma unroll
            for (int k = 0; k < NT; ++k) s += expf(v[k] - m);
            nfv[tid] = m + logf(s);
        }
        __syncwarp();
        if (tid < NT) fv[tid] = nfv[tid];
        __syncwarp();
    }
    if (tid == 0) {
        float m = -3.4e38f, v[NT];
        #pragma unroll
        for (int k = 0; k < NT; ++k) { v[k] = trans[STOP * NT + k] + fv[k]; m = fmaxf(m, v[k]); }
        float s = 0.f;
        #pragma unroll
        for (int k = 0; k < NT; ++k) s += expf(v[k] - m);
        out[0] = m + logf(s);
    }
}

// ---------------- launch ----------------
extern "C" void kernel_launch(void* const* d_in, const int* in_sizes, int n_in,
                              void* d_out, int out_size)
{
    const int*   sentence = (const int*)  d_in[0];
    const float* emb      = (const float*)d_in[1];
    const float* Wihf     = (const float*)d_in[2];
    const float* Whhf     = (const float*)d_in[3];
    const float* bf       = (const float*)d_in[4];
    const float* Wihb     = (const float*)d_in[5];
    const float* Whhb     = (const float*)d_in[6];
    const float* bb       = (const float*)d_in[7];
    const float* Wout     = (const float*)d_in[8];
    const float* bout     = (const float*)d_in[9];
    const float* trans    = (const float*)d_in[10];
    const float* h0       = (const float*)d_in[11];
    const float* c0       = (const float*)d_in[12];

    const size_t smem_bytes =
        (size_t)(2 * GROWS * E_DIM + H2 + E_DIM + GROWS + GROWS + ROWS_PER_CTA) * sizeof(float);
    cudaFuncSetAttribute(lstm_kernel, cudaFuncAttributeMaxDynamicSharedMemorySize, (int)smem_bytes);

    init_kernel<<<L_SEQ + 1, 128>>>(sentence, emb, h0);
    lstm_kernel<<<2 * NCTA_DIR, 256, smem_bytes>>>(Wihf, Whhf, bf, Wihb, Whhb, bb, c0);
    feats_kernel<<<L_SEQ, 384>>>(Wout, bout);
    crf_chunk_kernel<<<128, NT * NT>>>(trans);
    crf_final_kernel<<<1, 32>>>(trans, (float*)d_out);
}